// round 3
// baseline (speedup 1.0000x reference)
#include <cuda_runtime.h>
#include <cuda_bf16.h>

// Problem constants (fixed shapes for this problem)
#define NI 64      // input concentrations
#define NO 64      // output concentrations
#define NN 1024    // total N
#define NC 960     // regulated columns (N - I), global col = 64 + j
#define NWARM 25

typedef unsigned long long u64;

// ---------------- device scratch (static, allocation-free) ----------------
__device__ float g_S[NN * NC];        // sig_diff[k][j] for j -> global col 64+j  (3.93 MB)
__device__ float g_c0[NC];            // sum_{k<64} S[k][j]
__device__ float g_u[2][NC];          // unnormalized warmup state (ping/pong)
__device__ float g_spart[(NWARM + 1) * 30];  // per-step per-block partial sums (deterministic)
__device__ float g_bias[NC];          // bias_j for the batched step

// ---------------- packed f32x2 helpers (sm_100+ PTX) ----------------
__device__ __forceinline__ u64 pack2(float x, float y) {
    u64 r; asm("mov.b64 %0, {%1, %2};" : "=l"(r) : "f"(x), "f"(y)); return r;
}
__device__ __forceinline__ void unpack2(u64 v, float& x, float& y) {
    asm("mov.b64 {%0, %1}, %2;" : "=f"(x), "=f"(y) : "l"(v));
}
__device__ __forceinline__ void ffma2(u64& acc, u64 a, u64 b) {
    asm("fma.rn.f32x2 %0, %1, %2, %0;" : "+l"(acc) : "l"(a), "l"(b));
}

// ---------------- kernel 1: init state ----------------
__global__ void init_kernel() {
    int t = threadIdx.x;
    if (t < NC) g_u[0][t] = 1.0f / (float)NN;
    // zero all step partials; step-0 "s" = 1.0 encoded as row 0 = {1,0,0,...}
    for (int i = t; i < (NWARM + 1) * 30; i += blockDim.x) g_spart[i] = 0.0f;
    if (t == 0) g_spart[0] = 1.0f;
}

// ---------------- kernel 2: signature matrix ----------------
// S[k][j] = exp(-b|enh_k - id_{64+j}|) - exp(-b|inh_k - id_{64+j}|), rows 64..127 masked to 0
__global__ void sig_kernel(const float* __restrict__ ident, const float* __restrict__ enh,
                           const float* __restrict__ inh, const float* __restrict__ beta) {
    int j = blockIdx.x * blockDim.x + threadIdx.x;
    int k = blockIdx.y;
    if (j >= NC) return;
    float v = 0.0f;
    if (k < NI || k >= NI + NO) {
        float b = beta[0];
        float t = ident[NI + j];
        v = __expf(-b * fabsf(enh[k] - t)) - __expf(-b * fabsf(inh[k] - t));
    }
    g_S[k * NC + j] = v;
}

// ---------------- kernel 3: constant input-row contribution ----------------
__global__ void c0_kernel() {
    int j = blockIdx.x * blockDim.x + threadIdx.x;
    if (j >= NC) return;
    float s = 0.0f;
#pragma unroll 8
    for (int k = 0; k < NI; k++) s += g_S[k * NC + j];
    g_c0[j] = s;
}

// ---------------- warmup step ----------------
// state: u (unnormalized reg) + s (its sum).  conc_{64+j} = u_j / s  (if s>0)
// u'_j = relu( u_j*inv + (d/N) * ( (1/N)*c0_j + inv * sum_{k>=128} u_{k-64} S[k][j] ) )
// grid: 30 blocks x (32 j, 16 k-slices)
__global__ void step_kernel(int t, const float* __restrict__ delta) {
    __shared__ float su[NC];
    __shared__ float red[16][32];
    const float* u_in = g_u[t & 1];
    float* u_out = g_u[(t + 1) & 1];
    int tx = threadIdx.x, ty = threadIdx.y;
    int tid = ty * 32 + tx;
    for (int i = tid; i < NC; i += 512) su[i] = u_in[i];
    __syncthreads();

    int j = blockIdx.x * 32 + tx;
    float acc = 0.0f;
    const float* Sp = g_S + (size_t)(128 + ty) * NC + j;
#pragma unroll 7
    for (int m = 0; m < 56; m++)
        acc = fmaf(su[64 + ty + 16 * m], Sp[(size_t)m * 16 * NC], acc);
    red[ty][tx] = acc;
    __syncthreads();

    if (ty == 0) {
        float dot = 0.0f;
#pragma unroll
        for (int q = 0; q < 16; q++) dot += red[q][tx];
        // deterministic s from previous step's 30 block partials
        float s = 0.0f;
        const float* sp = g_spart + t * 30;
#pragma unroll
        for (int i = 0; i < 30; i++) s += sp[i];
        float inv = (s > 0.0f) ? 1.0f / s : 1.0f;
        float dN = delta[0] * (1.0f / (float)NN);
        float a = su[j] * inv + dN * ((1.0f / (float)NN) * g_c0[j] + inv * dot);
        float r = fmaxf(a, 0.0f);
        u_out[j] = r;
        float ssum = r;
#pragma unroll
        for (int off = 16; off > 0; off >>= 1)
            ssum += __shfl_xor_sync(0xffffffffu, ssum, off);
        if (tx == 0) g_spart[(t + 1) * 30 + blockIdx.x] = ssum;
    }
}

// ---------------- bias for the batched step ----------------
// bias_j = conc_warm_{64+j} + (d/N) * sum_{k>=64} conc_warm_k * S[k][j]
//        = u_j*inv + (d/N)*inv*dot_j   (S rows 64..127 are zero)
__global__ void bias_kernel(const float* __restrict__ delta) {
    __shared__ float su[NC];
    __shared__ float red[16][32];
    const float* u_in = g_u[NWARM & 1];
    int tx = threadIdx.x, ty = threadIdx.y;
    int tid = ty * 32 + tx;
    for (int i = tid; i < NC; i += 512) su[i] = u_in[i];
    __syncthreads();

    int j = blockIdx.x * 32 + tx;
    float acc = 0.0f;
    const float* Sp = g_S + (size_t)(128 + ty) * NC + j;
#pragma unroll 7
    for (int m = 0; m < 56; m++)
        acc = fmaf(su[64 + ty + 16 * m], Sp[(size_t)m * 16 * NC], acc);
    red[ty][tx] = acc;
    __syncthreads();

    if (ty == 0) {
        float dot = 0.0f;
#pragma unroll
        for (int q = 0; q < 16; q++) dot += red[q][tx];
        float s = 0.0f;
        const float* sp = g_spart + NWARM * 30;
#pragma unroll
        for (int i = 0; i < 30; i++) s += sp[i];
        float inv = (s > 0.0f) ? 1.0f / s : 1.0f;
        float dN = delta[0] * (1.0f / (float)NN);
        g_bias[j] = su[j] * inv + dN * inv * dot;
    }
}

// ---------------- main batched kernel ----------------
// Per row b: a_j = bias_j + (d/N) * sum_{k<64} x_{b,k} * S[k][j]
//            reg = relu(a); out_{b,o} = reg_o / sum_j reg_j   (o < 64)
// Block: 256 threads (8 warps), 32 rows/block, 4 rows/warp.
// Lane l owns column pairs j = 2l + 64m (m=0..14) -> m==0 pairs are the output cols.
__global__ void __launch_bounds__(256, 1)
main_kernel(const float* __restrict__ X, const float* __restrict__ delta,
            float* __restrict__ out, int B) {
    __shared__ float Xs[32 * 64];
    int tid = threadIdx.x;
    int lane = tid & 31, warp = tid >> 5;
    int row0 = blockIdx.x * 32;

    // stage X tile (32 rows x 64 cols) as float4
    {
        const float4* Xg = (const float4*)(X + (size_t)row0 * 64);
        float4* Xs4 = (float4*)Xs;
        Xs4[tid] = Xg[tid];
        Xs4[tid + 256] = Xg[tid + 256];
    }
    __syncthreads();
    float dN = delta[0] * (1.0f / (float)NN);

    u64 acc[4][15];
#pragma unroll
    for (int r = 0; r < 4; r++)
#pragma unroll
        for (int m = 0; m < 15; m++) acc[r][m] = 0ull;

    const float* xrow = Xs + (warp * 4) * 64;
#pragma unroll 4
    for (int k = 0; k < 64; k++) {
        const u64* Wk = (const u64*)(g_S + (size_t)k * NC);
        u64 w[15];
#pragma unroll
        for (int m = 0; m < 15; m++) w[m] = __ldg(&Wk[lane + 32 * m]);
        u64 xp[4];
#pragma unroll
        for (int r = 0; r < 4; r++) {
            float xv = xrow[r * 64 + k];
            xp[r] = pack2(xv, xv);
        }
#pragma unroll
        for (int m = 0; m < 15; m++)
#pragma unroll
            for (int r = 0; r < 4; r++) ffma2(acc[r][m], xp[r], w[m]);
    }

    // epilogue: bias + relu + row-sum + normalize + store first 64 cols
    float2 bias2[15];
#pragma unroll
    for (int m = 0; m < 15; m++) bias2[m] = ((const float2*)g_bias)[lane + 32 * m];

#pragma unroll
    for (int r = 0; r < 4; r++) {
        float o0 = 0.0f, o1 = 0.0f, part = 0.0f;
#pragma unroll
        for (int m = 0; m < 15; m++) {
            float ax, ay;
            unpack2(acc[r][m], ax, ay);
            float vx = fmaxf(fmaf(dN, ax, bias2[m].x), 0.0f);
            float vy = fmaxf(fmaf(dN, ay, bias2[m].y), 0.0f);
            if (m == 0) { o0 = vx; o1 = vy; }
            part += vx + vy;
        }
#pragma unroll
        for (int off = 16; off > 0; off >>= 1)
            part += __shfl_xor_sync(0xffffffffu, part, off);
        float invs = (part > 0.0f) ? 1.0f / part : 1.0f;
        int row = row0 + warp * 4 + r;
        if (row < B)
            ((float2*)out)[(size_t)row * 32 + lane] = make_float2(o0 * invs, o1 * invs);
    }
}

// ---------------- launcher ----------------
extern "C" void kernel_launch(void* const* d_in, const int* in_sizes, int n_in,
                              void* d_out, int out_size) {
    const float* X     = (const float*)d_in[0];  // (B, 64)
    const float* ident = (const float*)d_in[1];  // (1024,)
    const float* enh   = (const float*)d_in[2];  // (1024,)
    const float* inh   = (const float*)d_in[3];  // (1024,)
    const float* beta  = (const float*)d_in[4];  // (1,)
    const float* delta = (const float*)d_in[5];  // (1,)
    float* out = (float*)d_out;
    int B = in_sizes[0] / NI;

    init_kernel<<<1, 1024>>>();
    sig_kernel<<<dim3(4, NN), 256>>>(ident, enh, inh, beta);
    c0_kernel<<<4, 256>>>();
    for (int t = 0; t < NWARM; t++)
        step_kernel<<<30, dim3(32, 16)>>>(t, delta);
    bias_kernel<<<30, dim3(32, 16)>>>(delta);
    main_kernel<<<(B + 31) / 32, 256>>>(X, delta, out, B);
}

// round 4
// speedup vs baseline: 1.4016x; 1.4016x over previous
#include <cuda_runtime.h>
#include <cuda_bf16.h>

// Problem constants (fixed shapes)
#define NI 64      // input concentrations
#define NO 64      // output concentrations
#define NN 1024    // total N
#define NC 960     // regulated columns (N - I); global col = 64 + j
#define NK 896     // warmup contraction length (S rows 128..1023)
#define NWARM 25

typedef unsigned long long u64;

// ---------------- device scratch (static, allocation-free) ----------------
__device__ float g_S0[NI * NC];    // S rows 0..63, row-major [k][j]  (245 KB) — used by main GEMM
__device__ float g_ST[NC * NK];    // transposed S rows 128..1023: ST[j][k] = S[128+k][j]  (3.44 MB)
__device__ float g_c0[NC];         // sum_{k<64} S[k][j]
__device__ float g_u[2][NC];       // unnormalized warmup state (ping/pong)
__device__ float g_bias[NC];       // bias_j for the batched step

// ---------------- packed f32x2 helpers (sm_100+ PTX) ----------------
__device__ __forceinline__ u64 pack2(float x, float y) {
    u64 r; asm("mov.b64 %0, {%1, %2};" : "=l"(r) : "f"(x), "f"(y)); return r;
}
__device__ __forceinline__ void unpack2(u64 v, float& x, float& y) {
    asm("mov.b64 {%0, %1}, %2;" : "=f"(x), "=f"(y) : "l"(v));
}
__device__ __forceinline__ void ffma2(u64& acc, u64 a, u64 b) {
    asm("fma.rn.f32x2 %0, %1, %2, %0;" : "+l"(acc) : "l"(a), "l"(b));
}

// ---------------- setup: ST + S0 + c0 + u-init, fused ----------------
// Block j (grid 960, 256 threads):
//   ST[j][k] = exp(-b|enh_{128+k} - id_{64+j}|) - exp(-b|inh_{128+k} - id_{64+j}|)
//   S0[k][j] (k<64), c0[j] = sum_k S0[k][j], u0[j] = 1/N
__global__ void setup_kernel(const float* __restrict__ ident, const float* __restrict__ enh,
                             const float* __restrict__ inh, const float* __restrict__ beta) {
    int j = blockIdx.x;
    int tid = threadIdx.x;
    float b = beta[0];
    float idj = ident[NI + j];
    float* STr = g_ST + (size_t)j * NK;
#pragma unroll
    for (int it = 0; it < 4; it++) {          // 4*256 = 1024 >= 896
        int k = tid + it * 256;
        if (k < NK) {
            float e = __expf(-b * fabsf(enh[128 + k] - idj));
            float h = __expf(-b * fabsf(inh[128 + k] - idj));
            STr[k] = e - h;
        }
    }
    __shared__ float red[2];
    float v = 0.0f;
    if (tid < NI) {
        float e = __expf(-b * fabsf(enh[tid] - idj));
        float h = __expf(-b * fabsf(inh[tid] - idj));
        v = e - h;
        g_S0[tid * NC + j] = v;
    }
#pragma unroll
    for (int off = 16; off > 0; off >>= 1)
        v += __shfl_xor_sync(0xffffffffu, v, off);
    if (tid < NI && (tid & 31) == 0) red[tid >> 5] = v;
    __syncthreads();
    if (tid == 0) {
        g_c0[j] = red[0] + red[1];
        g_u[0][j] = 1.0f / (float)NN;
    }
}

// ---------------- warmup step / bias (one block per column j) ----------------
// conc_{64+j} at step t is u_t[j]/s_t (s_t = sum u_t; for t=0 unnormalized -> inv=1).
// mode 0: u_{t+1}[j] = relu( u[j]*inv + (d/N)*( c0[j]/N + inv*dot_j ) )
// mode 1: bias[j]    =       u[j]*inv + (d/N)*inv*dot_j
// where dot_j = sum_{k<896} ST[j][k] * u[64+k].
__global__ void step2_kernel(int t, int mode, const float* __restrict__ delta) {
    int j = blockIdx.x;
    int tid = threadIdx.x;   // 256
    const float* __restrict__ u_in = g_u[t & 1];

    // start scalar loads early (broadcast)
    float uj = u_in[j];
    float dN = delta[0] * (1.0f / (float)NN);
    float c0j = (mode == 0) ? g_c0[j] : 0.0f;

    float dot = 0.0f, s = 0.0f;
    if (tid < 224) {   // 224 * 4 = 896
        float4 w = ((const float4*)(g_ST + (size_t)j * NK))[tid];
        float4 u = ((const float4*)(u_in + 64))[tid];
        dot = w.x * u.x + w.y * u.y + w.z * u.z + w.w * u.w;
    }
    if (tid < 240) {   // 240 * 4 = 960
        float4 u = ((const float4*)u_in)[tid];
        s = (u.x + u.y) + (u.z + u.w);
    }
#pragma unroll
    for (int off = 16; off > 0; off >>= 1) {
        dot += __shfl_xor_sync(0xffffffffu, dot, off);
        s   += __shfl_xor_sync(0xffffffffu, s, off);
    }
    __shared__ float rd[8], rs[8];
    if ((tid & 31) == 0) { rd[tid >> 5] = dot; rs[tid >> 5] = s; }
    __syncthreads();
    if (tid == 0) {
        float D = 0.0f, S = 0.0f;
#pragma unroll
        for (int q = 0; q < 8; q++) { D += rd[q]; S += rs[q]; }
        float inv = (t == 0) ? 1.0f : ((S > 0.0f) ? 1.0f / S : 1.0f);
        if (mode == 0) {
            float a = uj * inv + dN * (c0j * (1.0f / (float)NN) + inv * D);
            g_u[(t + 1) & 1][j] = fmaxf(a, 0.0f);
        } else {
            g_bias[j] = uj * inv + dN * inv * D;
        }
    }
}

// ---------------- main batched kernel (unchanged from R2 — at FFMA2 floor) ----------------
// Per row b: a_j = bias_j + (d/N) * sum_{k<64} x_{b,k} * S0[k][j]
//            reg = relu(a); out_{b,o} = reg_o / sum_j reg_j   (o < 64)
__global__ void __launch_bounds__(256, 1)
main_kernel(const float* __restrict__ X, const float* __restrict__ delta,
            float* __restrict__ out, int B) {
    __shared__ float Xs[32 * 64];
    int tid = threadIdx.x;
    int lane = tid & 31, warp = tid >> 5;
    int row0 = blockIdx.x * 32;

    {
        const float4* Xg = (const float4*)(X + (size_t)row0 * 64);
        float4* Xs4 = (float4*)Xs;
        Xs4[tid] = Xg[tid];
        Xs4[tid + 256] = Xg[tid + 256];
    }
    __syncthreads();
    float dN = delta[0] * (1.0f / (float)NN);

    u64 acc[4][15];
#pragma unroll
    for (int r = 0; r < 4; r++)
#pragma unroll
        for (int m = 0; m < 15; m++) acc[r][m] = 0ull;

    const float* xrow = Xs + (warp * 4) * 64;
#pragma unroll 4
    for (int k = 0; k < 64; k++) {
        const u64* Wk = (const u64*)(g_S0 + (size_t)k * NC);
        u64 w[15];
#pragma unroll
        for (int m = 0; m < 15; m++) w[m] = __ldg(&Wk[lane + 32 * m]);
        u64 xp[4];
#pragma unroll
        for (int r = 0; r < 4; r++) {
            float xv = xrow[r * 64 + k];
            xp[r] = pack2(xv, xv);
        }
#pragma unroll
        for (int m = 0; m < 15; m++)
#pragma unroll
            for (int r = 0; r < 4; r++) ffma2(acc[r][m], xp[r], w[m]);
    }

    float2 bias2[15];
#pragma unroll
    for (int m = 0; m < 15; m++) bias2[m] = ((const float2*)g_bias)[lane + 32 * m];

#pragma unroll
    for (int r = 0; r < 4; r++) {
        float o0 = 0.0f, o1 = 0.0f, part = 0.0f;
#pragma unroll
        for (int m = 0; m < 15; m++) {
            float ax, ay;
            unpack2(acc[r][m], ax, ay);
            float vx = fmaxf(fmaf(dN, ax, bias2[m].x), 0.0f);
            float vy = fmaxf(fmaf(dN, ay, bias2[m].y), 0.0f);
            if (m == 0) { o0 = vx; o1 = vy; }
            part += vx + vy;
        }
#pragma unroll
        for (int off = 16; off > 0; off >>= 1)
            part += __shfl_xor_sync(0xffffffffu, part, off);
        float invs = (part > 0.0f) ? 1.0f / part : 1.0f;
        int row = row0 + warp * 4 + r;
        if (row < B)
            ((float2*)out)[(size_t)row * 32 + lane] = make_float2(o0 * invs, o1 * invs);
    }
}

// ---------------- launcher ----------------
extern "C" void kernel_launch(void* const* d_in, const int* in_sizes, int n_in,
                              void* d_out, int out_size) {
    const float* X     = (const float*)d_in[0];  // (B, 64)
    const float* ident = (const float*)d_in[1];  // (1024,)
    const float* enh   = (const float*)d_in[2];  // (1024,)
    const float* inh   = (const float*)d_in[3];  // (1024,)
    const float* beta  = (const float*)d_in[4];  // (1,)
    const float* delta = (const float*)d_in[5];  // (1,)
    float* out = (float*)d_out;
    int B = in_sizes[0] / NI;

    setup_kernel<<<NC, 256>>>(ident, enh, inh, beta);
    for (int t = 0; t < NWARM; t++)
        step2_kernel<<<NC, 256>>>(t, 0, delta);
    step2_kernel<<<NC, 256>>>(NWARM, 1, delta);
    main_kernel<<<(B + 31) / 32, 256>>>(X, delta, out, B);
}

// round 5
// speedup vs baseline: 1.5671x; 1.1181x over previous
#include <cuda_runtime.h>
#include <cuda_bf16.h>

// Problem constants (fixed shapes)
#define NI 64      // input concentrations
#define NO 64      // output concentrations
#define NN 1024    // total N
#define NC 960     // regulated columns (N - I); global col = 64 + j
#define NK 896     // warmup contraction length (S rows 128..1023)
#define NWARM 25
#define GRID_P 120         // persistent grid (< 148 SMs -> all co-resident)
#define NBAR 25            // grid barriers per launch

typedef unsigned long long u64;

// ---------------- device scratch (static, allocation-free) ----------------
__device__ float g_S0[NI * NC];     // S rows 0..63, row-major [k][j] (245 KB) — main GEMM weights
__device__ float g_u[2][NC];        // unnormalized warmup state (ping/pong)
__device__ float g_bias[NC];        // bias_j for the batched step
__device__ unsigned g_bar_count = 0;  // monotonic barrier arrivals (across replays)
__device__ unsigned g_bar_base  = 0;  // snapshot of count at launch start

// ---------------- packed f32x2 helpers ----------------
__device__ __forceinline__ u64 pack2(float x, float y) {
    u64 r; asm("mov.b64 %0, {%1, %2};" : "=l"(r) : "f"(x), "f"(y)); return r;
}
__device__ __forceinline__ void unpack2(u64 v, float& x, float& y) {
    asm("mov.b64 {%0, %1}, %2;" : "=f"(x), "=f"(y) : "l"(v));
}
__device__ __forceinline__ void ffma2(u64& acc, u64 a, u64 b) {
    asm("fma.rn.f32x2 %0, %1, %2, %0;" : "+l"(acc) : "l"(a), "l"(b));
}

__device__ __forceinline__ unsigned ld_acq(const unsigned* p) {
    unsigned v;
    asm volatile("ld.acquire.gpu.u32 %0, [%1];" : "=r"(v) : "l"(p) : "memory");
    return v;
}

// Grid-wide barrier, safe across graph replays (monotonic count + base snapshot).
__device__ __forceinline__ void grid_barrier(unsigned base, int i) {
    __syncthreads();
    if (threadIdx.x == 0) {
        __threadfence();
        atomicAdd(&g_bar_count, 1u);
        unsigned target = base + (unsigned)(i + 1) * GRID_P;
        unsigned v;
        do { v = ld_acq(&g_bar_count); } while ((int)(v - target) < 0);
    }
    __syncthreads();
}

// ---------------- fused setup + 25 warmup steps + bias (persistent) ----------------
// Block b owns columns col = 8b..8b+7 (one warp per column).
// Warp c, lane l holds ST[col][k] for k = l + 32m (m=0..27) in registers, where
// ST[col][k] = S[128+k][64+col] (exp-kernel difference), built from factorized exps.
// Warmup recurrence (identical math to the R3 kernel, which passed at 3.4e-7):
//   dot_j = sum_k ST[j][k] * u[64+k];  s = sum(u);  inv = (t==0)?1:(s>0?1/s:1)
//   u'_j = relu( u_j*inv + dN*( c0_j/N + inv*dot_j ) )       [steps 0..24]
//   bias_j =      u_j*inv + dN*inv*dot_j                      [final]
__global__ void __launch_bounds__(256, 1)
warm_kernel(const float* __restrict__ ident, const float* __restrict__ enh,
            const float* __restrict__ inh, const float* __restrict__ beta,
            const float* __restrict__ delta) {
    __shared__ float sEnhP[NK], sEnhM[NK], sInhP[NK], sInhM[NK];
    __shared__ float su[NC];
    __shared__ float spart[8];
    __shared__ unsigned s_base;

    int tid = threadIdx.x;
    int lane = tid & 31, wrp = tid >> 5;
    int col = blockIdx.x * 8 + wrp;          // 0..959

    if (tid == 0) s_base = g_bar_base;

    float b = beta[0];
    float dN = delta[0] * (1.0f / (float)NN);

    // factorized exp tables for rows 128..1023 (7 exps/thread instead of 1.8M total)
    for (int k = tid; k < NK; k += 256) {
        float e = enh[128 + k], h = inh[128 + k];
        sEnhP[k] = __expf(-b * e);
        sEnhM[k] = __expf( b * e);
        sInhP[k] = __expf(-b * h);
        sInhM[k] = __expf( b * h);
    }
    float idj = ident[NI + col];
    float IjP = __expf( b * idj);
    float IjM = __expf(-b * idj);
    bool bpos = (b >= 0.0f);
    __syncthreads();
    unsigned base = s_base;

    // ST weights into registers: exp(-b|x-y|) = min(e^{-bx}e^{by}, e^{bx}e^{-by}) for b>=0
    float ST[28];
#pragma unroll
    for (int m = 0; m < 28; m++) {
        int k = lane + 32 * m;
        float e1 = sEnhP[k] * IjP, e2 = sEnhM[k] * IjM;
        float i1 = sInhP[k] * IjP, i2 = sInhM[k] * IjM;
        float ev = bpos ? fminf(e1, e2) : fmaxf(e1, e2);
        float iv = bpos ? fminf(i1, i2) : fmaxf(i1, i2);
        ST[m] = ev - iv;
    }

    // S0 rows (k<64) for the main GEMM + c0 = column sum
    float c0 = 0.0f;
#pragma unroll
    for (int q = 0; q < 2; q++) {
        int k = lane + 32 * q;
        float v = __expf(-b * fabsf(enh[k] - idj)) - __expf(-b * fabsf(inh[k] - idj));
        g_S0[k * NC + col] = v;
        c0 += v;
    }
#pragma unroll
    for (int off = 16; off > 0; off >>= 1) c0 += __shfl_xor_sync(0xffffffffu, c0, off);
    // all lanes now hold c0(col)

    // ---- step 0: u = const 1/N, inv = 1 ----
    {
        float acc = 0.0f;
#pragma unroll
        for (int m = 0; m < 28; m++) acc += ST[m];
#pragma unroll
        for (int off = 16; off > 0; off >>= 1) acc += __shfl_xor_sync(0xffffffffu, acc, off);
        if (lane == 0) {
            float dot = acc * (1.0f / (float)NN);
            float a = (1.0f / (float)NN) + dN * (c0 * (1.0f / (float)NN) + dot);
            g_u[1][col] = fmaxf(a, 0.0f);
        }
    }
    grid_barrier(base, 0);

    // ---- steps 1..24 + bias (t == NWARM) ----
    for (int t = 1; t <= NWARM; t++) {
        const float* __restrict__ uin = g_u[t & 1];
        float s4 = 0.0f;
        if (tid < 240) {
            float4 v = ((const float4*)uin)[tid];
            ((float4*)su)[tid] = v;
            s4 = (v.x + v.y) + (v.z + v.w);
        }
#pragma unroll
        for (int off = 16; off > 0; off >>= 1) s4 += __shfl_xor_sync(0xffffffffu, s4, off);
        if (lane == 0) spart[wrp] = s4;
        __syncthreads();
        float s = 0.0f;
#pragma unroll
        for (int q = 0; q < 8; q++) s += spart[q];   // fixed order -> identical in every block
        float inv = (s > 0.0f) ? 1.0f / s : 1.0f;

        float acc = 0.0f;
#pragma unroll
        for (int m = 0; m < 28; m++)
            acc = fmaf(ST[m], su[64 + lane + 32 * m], acc);
#pragma unroll
        for (int off = 16; off > 0; off >>= 1) acc += __shfl_xor_sync(0xffffffffu, acc, off);

        if (lane == 0) {
            float uj = su[col];
            if (t < NWARM) {
                float a = uj * inv + dN * (c0 * (1.0f / (float)NN) + inv * acc);
                g_u[(t + 1) & 1][col] = fmaxf(a, 0.0f);
            } else {
                g_bias[col] = uj * inv + dN * inv * acc;
            }
        }
        if (t < NWARM) grid_barrier(base, t);
    }

    // publish new base for the next graph replay (all blocks passed the last
    // barrier before block 0 reaches here; nobody reads g_bar_base this launch)
    if (blockIdx.x == 0 && tid == 0) g_bar_base = base + NBAR * GRID_P;
}

// ---------------- main batched kernel (unchanged — at FFMA2 floor) ----------------
// Per row b: a_j = bias_j + (d/N) * sum_{k<64} x_{b,k} * S0[k][j]
//            reg = relu(a); out_{b,o} = reg_o / sum_j reg_j   (o < 64)
__global__ void __launch_bounds__(256, 1)
main_kernel(const float* __restrict__ X, const float* __restrict__ delta,
            float* __restrict__ out, int B) {
    __shared__ float Xs[32 * 64];
    int tid = threadIdx.x;
    int lane = tid & 31, warp = tid >> 5;
    int row0 = blockIdx.x * 32;

    {
        const float4* Xg = (const float4*)(X + (size_t)row0 * 64);
        float4* Xs4 = (float4*)Xs;
        Xs4[tid] = Xg[tid];
        Xs4[tid + 256] = Xg[tid + 256];
    }
    __syncthreads();
    float dN = delta[0] * (1.0f / (float)NN);

    u64 acc[4][15];
#pragma unroll
    for (int r = 0; r < 4; r++)
#pragma unroll
        for (int m = 0; m < 15; m++) acc[r][m] = 0ull;

    const float* xrow = Xs + (warp * 4) * 64;
#pragma unroll 4
    for (int k = 0; k < 64; k++) {
        const u64* Wk = (const u64*)(g_S0 + (size_t)k * NC);
        u64 w[15];
#pragma unroll
        for (int m = 0; m < 15; m++) w[m] = __ldg(&Wk[lane + 32 * m]);
        u64 xp[4];
#pragma unroll
        for (int r = 0; r < 4; r++) {
            float xv = xrow[r * 64 + k];
            xp[r] = pack2(xv, xv);
        }
#pragma unroll
        for (int m = 0; m < 15; m++)
#pragma unroll
            for (int r = 0; r < 4; r++) ffma2(acc[r][m], xp[r], w[m]);
    }

    float2 bias2[15];
#pragma unroll
    for (int m = 0; m < 15; m++) bias2[m] = ((const float2*)g_bias)[lane + 32 * m];

#pragma unroll
    for (int r = 0; r < 4; r++) {
        float o0 = 0.0f, o1 = 0.0f, part = 0.0f;
#pragma unroll
        for (int m = 0; m < 15; m++) {
            float ax, ay;
            unpack2(acc[r][m], ax, ay);
            float vx = fmaxf(fmaf(dN, ax, bias2[m].x), 0.0f);
            float vy = fmaxf(fmaf(dN, ay, bias2[m].y), 0.0f);
            if (m == 0) { o0 = vx; o1 = vy; }
            part += vx + vy;
        }
#pragma unroll
        for (int off = 16; off > 0; off >>= 1)
            part += __shfl_xor_sync(0xffffffffu, part, off);
        float invs = (part > 0.0f) ? 1.0f / part : 1.0f;
        int row = row0 + warp * 4 + r;
        if (row < B)
            ((float2*)out)[(size_t)row * 32 + lane] = make_float2(o0 * invs, o1 * invs);
    }
}

// ---------------- launcher (2 graph nodes) ----------------
extern "C" void kernel_launch(void* const* d_in, const int* in_sizes, int n_in,
                              void* d_out, int out_size) {
    const float* X     = (const float*)d_in[0];  // (B, 64)
    const float* ident = (const float*)d_in[1];  // (1024,)
    const float* enh   = (const float*)d_in[2];  // (1024,)
    const float* inh   = (const float*)d_in[3];  // (1024,)
    const float* beta  = (const float*)d_in[4];  // (1,)
    const float* delta = (const float*)d_in[5];  // (1,)
    float* out = (float*)d_out;
    int B = in_sizes[0] / NI;

    warm_kernel<<<GRID_P, 256>>>(ident, enh, inh, beta, delta);
    main_kernel<<<(B + 31) / 32, 256>>>(X, delta, out, B);
}